// round 16
// baseline (speedup 1.0000x reference)
#include <cuda_runtime.h>
#include <cuda_bf16.h>
#include <math.h>
#include <stdint.h>

// ---------------------------------------------------------------------------
// BitNetV3 MLP via IMMA (mma.sync.m16n8k32.s8) tensor cores.
// out = BitLinear(silu(BitLinear(x,Wg)) * BitLinear(x,Wu), Wd)
// Round 16: gate+up GEMMs FUSED in one kernel (shared A tile, h written once,
// no gate roundtrip). Down GEMM and all prep identical to round 11 (3214us).
// T=4096 tokens, H=2048, I=8192. Integer GEMM math is bit-exact.
// ---------------------------------------------------------------------------

#define T_TOK 4096
#define H_DIM 2048
#define I_DIM 8192

#define NORM_2048 0.022097086912079608f   // 1/sqrt(2048)
#define NORM_8192 0.011048543456039804f   // 1/sqrt(8192)

// ------------------------- scratch (allocation-free) -----------------------
__device__ __align__(16) int    g_qx1[T_TOK * H_DIM / 4];            //  8 MB
__device__ __align__(16) int    g_qx2[T_TOK * I_DIM / 4];            // 32 MB
__device__ float  g_as1[T_TOK];
__device__ float  g_as2[T_TOK];
__device__ __align__(16) int    g_qwg[I_DIM * H_DIM / 4];            // 16 MB
__device__ __align__(16) int    g_qwu[I_DIM * H_DIM / 4];            // 16 MB
__device__ __align__(16) int    g_qwd[H_DIM * I_DIM / 4];            // 16 MB
__device__ float  g_ws[4];
__device__ float  g_part[3 * 512];
__device__ float  g_gate[(size_t)T_TOK * I_DIM];                     // h buffer

// ----------------------------- PTX helpers ---------------------------------
__device__ __forceinline__ uint32_t s2u(const void* p) {
    uint32_t a;
    asm("{ .reg .u64 t; cvta.to.shared.u64 t, %1; cvt.u32.u64 %0, t; }"
        : "=r"(a) : "l"(p));
    return a;
}
__device__ __forceinline__ void cp16(uint32_t d, const void* s) {
    asm volatile("cp.async.cg.shared.global [%0], [%1], 16;" :: "r"(d), "l"(s));
}
__device__ __forceinline__ void cp_commit() { asm volatile("cp.async.commit_group;"); }
__device__ __forceinline__ void cp_wait1()  { asm volatile("cp.async.wait_group 1;"); }

__device__ __forceinline__ void ldm_x4(uint32_t* r, uint32_t addr) {
    asm volatile("ldmatrix.sync.aligned.m8n8.x4.shared.b16 {%0,%1,%2,%3}, [%4];"
                 : "=r"(r[0]), "=r"(r[1]), "=r"(r[2]), "=r"(r[3]) : "r"(addr));
}
__device__ __forceinline__ void mma_s8(int* d, const uint32_t* a,
                                       uint32_t b0, uint32_t b1) {
    asm volatile(
        "mma.sync.aligned.m16n8k32.row.col.s32.s8.s8.s32 "
        "{%0,%1,%2,%3}, {%4,%5,%6,%7}, {%8,%9}, {%0,%1,%2,%3};"
        : "+r"(d[0]), "+r"(d[1]), "+r"(d[2]), "+r"(d[3])
        : "r"(a[0]), "r"(a[1]), "r"(a[2]), "r"(a[3]), "r"(b0), "r"(b1));
}

// --------------- batched weight prep (3 weights in 3 launches) -------------
__global__ void abs_sum_all(const float4* __restrict__ w0,
                            const float4* __restrict__ w1,
                            const float4* __restrict__ w2,
                            int n4, float* __restrict__ part) {
    const float4* w = (blockIdx.y == 0) ? w0 : (blockIdx.y == 1) ? w1 : w2;
    float s0 = 0.f, s1 = 0.f, s2 = 0.f, s3 = 0.f;
    int i = blockIdx.x * 256 + threadIdx.x;
    const int stride = 512 * 256;
    for (; i + 3 * stride < n4; i += 4 * stride) {
        float4 a = w[i];
        float4 b = w[i + stride];
        float4 c = w[i + 2 * stride];
        float4 d = w[i + 3 * stride];
        s0 += fabsf(a.x) + fabsf(a.y) + fabsf(a.z) + fabsf(a.w);
        s1 += fabsf(b.x) + fabsf(b.y) + fabsf(b.z) + fabsf(b.w);
        s2 += fabsf(c.x) + fabsf(c.y) + fabsf(c.z) + fabsf(c.w);
        s3 += fabsf(d.x) + fabsf(d.y) + fabsf(d.z) + fabsf(d.w);
    }
    for (; i < n4; i += stride) {
        float4 a = w[i];
        s0 += fabsf(a.x) + fabsf(a.y) + fabsf(a.z) + fabsf(a.w);
    }
    __shared__ float red[256];
    red[threadIdx.x] = (s0 + s1) + (s2 + s3);
    __syncthreads();
    for (int off = 128; off > 0; off >>= 1) {
        if ((int)threadIdx.x < off) red[threadIdx.x] += red[threadIdx.x + off];
        __syncthreads();
    }
    if (threadIdx.x == 0) part[blockIdx.y * 512 + blockIdx.x] = red[0];
}

__global__ void abs_final_all(const float* __restrict__ part, long long n,
                              float* __restrict__ ws) {
    __shared__ double red[256];
    double s = 0.0;
    for (int i = threadIdx.x; i < 512; i += 256)
        s += (double)part[blockIdx.x * 512 + i];
    red[threadIdx.x] = s;
    __syncthreads();
    for (int off = 128; off > 0; off >>= 1) {
        if ((int)threadIdx.x < off) red[threadIdx.x] += red[threadIdx.x + off];
        __syncthreads();
    }
    if (threadIdx.x == 0)
        ws[blockIdx.x] = fmaxf((float)(red[0] / (double)n), 1e-5f);
}

__global__ void quant_pack_all(const float* __restrict__ w0,
                               const float* __restrict__ w1,
                               const float* __restrict__ w2,
                               const float* __restrict__ sc,
                               int* __restrict__ q0, int* __restrict__ q1,
                               int* __restrict__ q2, int n4) {
    int i = blockIdx.x * 256 + threadIdx.x;
    if (i >= n4) return;
    const int which = blockIdx.y;
    const float* w = (which == 0) ? w0 : (which == 1) ? w1 : w2;
    int* q = (which == 0) ? q0 : (which == 1) ? q1 : q2;
    float s = sc[which];
    float4 v = reinterpret_cast<const float4*>(w)[i];
    int a = (int)fminf(fmaxf(rintf(v.x / s), -1.f), 1.f);
    int b = (int)fminf(fmaxf(rintf(v.y / s), -1.f), 1.f);
    int c = (int)fminf(fmaxf(rintf(v.z / s), -1.f), 1.f);
    int d = (int)fminf(fmaxf(rintf(v.w / s), -1.f), 1.f);
    q[i] = (a & 0xFF) | ((b & 0xFF) << 8) | ((c & 0xFF) << 16) | ((d & 0xFF) << 24);
}

// --------------- FWHT (last axis) + per-token int8 quant + pack ------------
template <int N, int TPB>
__global__ void fwht_quant(const float* __restrict__ X, int* __restrict__ Q,
                           float* __restrict__ scales, float norm) {
    __shared__ float s[N];
    __shared__ float red[TPB];
    const int t = blockIdx.x;
    const float* x = X + (size_t)t * N;

    for (int i = threadIdx.x; i < N; i += TPB) s[i] = x[i];
    __syncthreads();

    for (int h = 1; h < N; h <<= 1) {
        for (int p = threadIdx.x; p < N / 2; p += TPB) {
            int i = ((p & ~(h - 1)) << 1) | (p & (h - 1));
            float a = s[i], b = s[i + h];
            s[i] = a + b;
            s[i + h] = a - b;
        }
        __syncthreads();
    }

    float m = 0.f;
    for (int i = threadIdx.x; i < N; i += TPB)
        m = fmaxf(m, fabsf(s[i] * norm));
    red[threadIdx.x] = m;
    __syncthreads();
    for (int off = TPB / 2; off > 0; off >>= 1) {
        if ((int)threadIdx.x < off)
            red[threadIdx.x] = fmaxf(red[threadIdx.x], red[threadIdx.x + off]);
        __syncthreads();
    }
    float scale = 127.f / fmaxf(red[0], 1e-5f);
    if (threadIdx.x == 0) scales[t] = scale;

    for (int i = threadIdx.x; i < N / 4; i += TPB) {
        float v0 = s[4 * i + 0] * norm * scale;
        float v1 = s[4 * i + 1] * norm * scale;
        float v2 = s[4 * i + 2] * norm * scale;
        float v3 = s[4 * i + 3] * norm * scale;
        int q0 = (int)fminf(fmaxf(rintf(v0), -128.f), 127.f);
        int q1 = (int)fminf(fmaxf(rintf(v1), -128.f), 127.f);
        int q2 = (int)fminf(fmaxf(rintf(v2), -128.f), 127.f);
        int q3 = (int)fminf(fmaxf(rintf(v3), -128.f), 127.f);
        Q[(size_t)t * (N / 4) + i] = (q0 & 0xFF) | ((q1 & 0xFF) << 8)
                                   | ((q2 & 0xFF) << 16) | ((q3 & 0xFF) << 24);
    }
}

// ------------------- FUSED gate+up IMMA GEMM (round 16) --------------------
// CTA: M=128, N=64 slice of BOTH gate and up. 8 warps (4M x 2N), warp tile
// 32x32 per matrix. Stage: A 16KB + Bg 8KB + Bu 8KB = 32KB; 3-stage ring,
// distance 1, one __syncthreads per chunk after wait_group (R11 pattern).
// Epilogue: h = silu(gate)*up written once to C (no gate roundtrip).
#define FSTAGE 32768
#define FUSED_SMEM (3 * FSTAGE)

__global__ __launch_bounds__(256, 2)
void gemm_fused_gu(const char* __restrict__ A,    // [T][K] int8 row-major
                   const char* __restrict__ Bg,   // [I][K] int8 row-major
                   const char* __restrict__ Bu,   // [I][K]
                   float* __restrict__ C,         // [T][I] f32 (h)
                   int O, int K,
                   const float* __restrict__ actScale,
                   const float* __restrict__ wScale) {
    extern __shared__ __align__(1024) char smem[];
    const uint32_t S0 = s2u(smem);   // stage s: A +s*32KB, Bg +16KB, Bu +24KB

    const int tid = threadIdx.x;
    const int lane = tid & 31, w = tid >> 5;
    const int wm = w >> 1, wn = w & 1;       // warp grid 4(M) x 2(N of 64)
    const int blockM = blockIdx.y * 128, blockN = blockIdx.x * 64;

    const int aRow = wm * 32 + (lane & 7) + ((lane >> 3) & 1) * 8;
    const uint32_t aKh = ((lane >> 4) & 1) * 16;
    const uint32_t aQ  = (uint32_t)(aRow & 7) << 4;
    const int bRow = wn * 32 + (lane & 7) + ((lane >> 4) & 1) * 8;
    const uint32_t bKh = ((lane >> 3) & 1) * 16;
    const uint32_t bQ  = (uint32_t)(bRow & 7) << 4;

    int accg[2][4][4], accu[2][4][4];
#pragma unroll
    for (int i = 0; i < 2; i++)
#pragma unroll
        for (int j = 0; j < 4; j++)
#pragma unroll
            for (int k = 0; k < 4; k++) { accg[i][j][k] = 0; accu[i][j][k] = 0; }

    const char* gA = A  + (size_t)blockM * K;
    const char* gG = Bg + (size_t)blockN * K;
    const char* gU = Bu + (size_t)blockN * K;
    const int nC = K >> 7;

    // loader: A 1024 + Bg 512 + Bu 512 = 2048 16B segs over 256 thr -> 8 each
#define LOAD_CHUNK(stage, kt)                                                 \
    do {                                                                      \
        const uint32_t dA = S0 + (stage) * FSTAGE;                            \
        _Pragma("unroll")                                                     \
        for (int i = 0; i < 8; i++) {                                         \
            int g = i * 256 + tid;                                            \
            if (g < 1024) {                                                   \
                uint32_t off = (uint32_t)g * 16;                              \
                uint32_t sw = off ^ ((off >> 3) & 0x70);                      \
                cp16(dA + sw, gA + (size_t)(g >> 3) * K + (kt) + (g & 7) * 16); \
            } else if (g < 1536) {                                            \
                int h2 = g - 1024;                                            \
                uint32_t off = (uint32_t)h2 * 16;                             \
                uint32_t sw = off ^ ((off >> 3) & 0x70);                      \
                cp16(dA + 16384 + sw,                                         \
                     gG + (size_t)(h2 >> 3) * K + (kt) + (h2 & 7) * 16);      \
            } else {                                                          \
                int h2 = g - 1536;                                            \
                uint32_t off = (uint32_t)h2 * 16;                             \
                uint32_t sw = off ^ ((off >> 3) & 0x70);                      \
                cp16(dA + 24576 + sw,                                         \
                     gU + (size_t)(h2 >> 3) * K + (kt) + (h2 & 7) * 16);      \
            }                                                                 \
        }                                                                     \
        cp_commit();                                                          \
    } while (0)

    LOAD_CHUNK(0, 0);

    int st = 0;
    for (int c = 0; c < nC; c++) {
        if (c + 1 < nC) {
            int ns = st + 1; if (ns == 3) ns = 0;
            LOAD_CHUNK(ns, (c + 1) << 7);
        } else {
            cp_commit();
        }
        cp_wait1();
        __syncthreads();

        const uint32_t aBase = S0 + st * FSTAGE + (uint32_t)aRow * 128;
        const uint32_t gBase = S0 + st * FSTAGE + 16384 + (uint32_t)bRow * 128;
        const uint32_t uBase = S0 + st * FSTAGE + 24576 + (uint32_t)bRow * 128;
#pragma unroll
        for (int ks = 0; ks < 4; ks++) {
            uint32_t Af[2][4], Gf[2][4], Uf[2][4];
#pragma unroll
            for (int mr = 0; mr < 2; mr++)
                ldm_x4(Af[mr], aBase + mr * (16 * 128)
                               + (((uint32_t)(ks * 32) + aKh) ^ aQ));
#pragma unroll
            for (int ng = 0; ng < 2; ng++) {
                ldm_x4(Gf[ng], gBase + ng * (16 * 128)
                               + (((uint32_t)(ks * 32) + bKh) ^ bQ));
                ldm_x4(Uf[ng], uBase + ng * (16 * 128)
                               + (((uint32_t)(ks * 32) + bKh) ^ bQ));
            }
#pragma unroll
            for (int mr = 0; mr < 2; mr++)
#pragma unroll
                for (int nb = 0; nb < 4; nb++) {
                    mma_s8(accg[mr][nb], Af[mr],
                           Gf[nb >> 1][(nb & 1) * 2], Gf[nb >> 1][(nb & 1) * 2 + 1]);
                    mma_s8(accu[mr][nb], Af[mr],
                           Uf[nb >> 1][(nb & 1) * 2], Uf[nb >> 1][(nb & 1) * 2 + 1]);
                }
        }
        if (++st == 3) st = 0;
    }
#undef LOAD_CHUNK

    // epilogue: h = silu(g)*u, single write
    const float wG = wScale[0], wU = wScale[1];
    const int r = lane >> 2, cq = (lane & 3) * 2;
#pragma unroll
    for (int mr = 0; mr < 2; mr++) {
#pragma unroll
        for (int half = 0; half < 2; half++) {
            const int m = blockM + wm * 32 + mr * 16 + half * 8 + r;
            const float inv = 1.f / __ldg(&actScale[m]);
            const float fg = wG * inv, fu = wU * inv;
            float* crow = C + (size_t)m * O + blockN + wn * 32;
#pragma unroll
            for (int nb = 0; nb < 4; nb++) {
                float g0 = (float)accg[mr][nb][half * 2]     * fg;
                float g1 = (float)accg[mr][nb][half * 2 + 1] * fg;
                float u0 = (float)accu[mr][nb][half * 2]     * fu;
                float u1 = (float)accu[mr][nb][half * 2 + 1] * fu;
                float2 v;
                v.x = (g0 / (1.f + expf(-g0))) * u0;
                v.y = (g1 / (1.f + expf(-g1))) * u1;
                *reinterpret_cast<float2*>(crow + nb * 8 + cq) = v;
            }
        }
    }
}

// ------------------- down-projection IMMA GEMM (round 11) ------------------
#define STAGE_BYTES 32768
#define GEMM_SMEM   (3 * STAGE_BYTES)

__global__ __launch_bounds__(256, 2)
void gemm_imma(const char* __restrict__ A,   // [M_total][K] int8 row-major
               const char* __restrict__ Bw,  // [O][K]      int8 row-major
               float* __restrict__ C,        // [M_total][O] f32
               int O, int K,
               const float* __restrict__ actScale,
               const float* __restrict__ wScale) {
    extern __shared__ __align__(1024) char smem[];
    const uint32_t S0 = s2u(smem);

    const int tid = threadIdx.x;
    const int lane = tid & 31, w = tid >> 5;
    const int wm = w >> 1, wn = w & 1;
    const int blockM = blockIdx.y * 128, blockN = blockIdx.x * 128;

    const int aRow = wm * 32 + (lane & 7) + ((lane >> 3) & 1) * 8;
    const uint32_t aKh = ((lane >> 4) & 1) * 16;
    const uint32_t aQ  = (uint32_t)(aRow & 7) << 4;
    const int bRow = wn * 64 + (lane & 7) + ((lane >> 4) & 1) * 8;
    const uint32_t bKh = ((lane >> 3) & 1) * 16;
    const uint32_t bQ  = (uint32_t)(bRow & 7) << 4;

    int acc[2][8][4];
#pragma unroll
    for (int i = 0; i < 2; i++)
#pragma unroll
        for (int j = 0; j < 8; j++)
#pragma unroll
            for (int k = 0; k < 4; k++) acc[i][j][k] = 0;

    const char* gA = A  + (size_t)blockM * K;
    const char* gB = Bw + (size_t)blockN * K;
    const int nC = K >> 7;

#define LOAD_CHUNK(stage, kt)                                                 \
    do {                                                                      \
        const uint32_t dA = S0 + (stage) * STAGE_BYTES;                       \
        const uint32_t dB = dA + 16384;                                       \
        _Pragma("unroll")                                                     \
        for (int i = 0; i < 4; i++) {                                         \
            int g = i * 256 + tid;                                            \
            uint32_t off = (uint32_t)g * 16;                                  \
            uint32_t sw = off ^ ((off >> 3) & 0x70);                          \
            int row = g >> 3, cc = (g & 7) * 16;                              \
            cp16(dA + sw, gA + (size_t)row * K + (kt) + cc);                  \
            cp16(dB + sw, gB + (size_t)row * K + (kt) + cc);                  \
        }                                                                     \
        cp_commit();                                                          \
    } while (0)

    LOAD_CHUNK(0, 0);

    int st = 0;
    for (int c = 0; c < nC; c++) {
        if (c + 1 < nC) {
            int ns = st + 1; if (ns == 3) ns = 0;
            LOAD_CHUNK(ns, (c + 1) << 7);
        } else {
            cp_commit();
        }
        cp_wait1();
        __syncthreads();

        const uint32_t aBase = S0 + st * STAGE_BYTES + (uint32_t)aRow * 128;
        const uint32_t bBase = S0 + st * STAGE_BYTES + 16384 + (uint32_t)bRow * 128;
#pragma unroll
        for (int ks = 0; ks < 4; ks++) {
            uint32_t Af[2][4], Bf[4][4];
#pragma unroll
            for (int mr = 0; mr < 2; mr++)
                ldm_x4(Af[mr], aBase + mr * (16 * 128)
                               + (((uint32_t)(ks * 32) + aKh) ^ aQ));
#pragma unroll
            for (int ng = 0; ng < 4; ng++)
                ldm_x4(Bf[ng], bBase + ng * (16 * 128)
                               + (((uint32_t)(ks * 32) + bKh) ^ bQ));
#pragma unroll
            for (int mr = 0; mr < 2; mr++)
#pragma unroll
                for (int nb = 0; nb < 8; nb++)
                    mma_s8(acc[mr][nb], Af[mr],
                           Bf[nb >> 1][(nb & 1) * 2],
                           Bf[nb >> 1][(nb & 1) * 2 + 1]);
        }
        if (++st == 3) st = 0;
    }
#undef LOAD_CHUNK

    const float wS = wScale[0];
    const int r = lane >> 2, cq = (lane & 3) * 2;
#pragma unroll
    for (int mr = 0; mr < 2; mr++) {
#pragma unroll
        for (int half = 0; half < 2; half++) {
            const int m = blockM + wm * 32 + mr * 16 + half * 8 + r;
            const float f = wS / __ldg(&actScale[m]);
            float* crow = C + (size_t)m * O + blockN + wn * 64;
#pragma unroll
            for (int nb = 0; nb < 8; nb++) {
                float2 v;
                v.x = (float)acc[mr][nb][half * 2]     * f;
                v.y = (float)acc[mr][nb][half * 2 + 1] * f;
                *reinterpret_cast<float2*>(crow + nb * 8 + cq) = v;
            }
        }
    }
}

// ------------------------------- launcher ----------------------------------
extern "C" void kernel_launch(void* const* d_in, const int* in_sizes, int n_in,
                              void* d_out, int out_size) {
    const float* x  = (const float*)d_in[0];
    const float* wg = (const float*)d_in[1];
    const float* wu = (const float*)d_in[2];
    const float* wd = (const float*)d_in[3];
    float* out = (float*)d_out;

    void* p;
    cudaGetSymbolAddress(&p, g_qx1);  int*   qx1  = (int*)p;
    cudaGetSymbolAddress(&p, g_qx2);  int*   qx2  = (int*)p;
    cudaGetSymbolAddress(&p, g_as1);  float* as1  = (float*)p;
    cudaGetSymbolAddress(&p, g_as2);  float* as2  = (float*)p;
    cudaGetSymbolAddress(&p, g_qwg);  int*   qwg  = (int*)p;
    cudaGetSymbolAddress(&p, g_qwu);  int*   qwu  = (int*)p;
    cudaGetSymbolAddress(&p, g_qwd);  int*   qwd  = (int*)p;
    cudaGetSymbolAddress(&p, g_ws);   float* ws   = (float*)p;
    cudaGetSymbolAddress(&p, g_part); float* part = (float*)p;
    cudaGetSymbolAddress(&p, g_gate); float* hbuf = (float*)p;

    cudaFuncSetAttribute(gemm_fused_gu, cudaFuncAttributeMaxDynamicSharedMemorySize, FUSED_SMEM);
    cudaFuncSetAttribute(gemm_imma,     cudaFuncAttributeMaxDynamicSharedMemorySize, GEMM_SMEM);

    const long long nW = (long long)I_DIM * H_DIM;
    const int n4 = (int)(nW / 4);

    // launches 0-2: weight scales + ternary pack
    abs_sum_all<<<dim3(512, 3), 256>>>((const float4*)wg, (const float4*)wu,
                                       (const float4*)wd, n4, part);
    abs_final_all<<<3, 256>>>(part, nW, ws);
    quant_pack_all<<<dim3((n4 + 255) / 256, 3), 256>>>(wg, wu, wd, ws,
                                                       qwg, qwu, qwd, n4);

    // launch 3: FWHT(2048) + int8 quant of input
    fwht_quant<H_DIM, 256><<<T_TOK, 256>>>(x, qx1, as1, NORM_2048);

    // launch 4: fused h = silu(xq@Wg^T) * (xq@Wu^T)
    gemm_fused_gu<<<dim3(I_DIM / 64, T_TOK / 128), 256, FUSED_SMEM>>>(
        (const char*)qx1, (const char*)qwg, (const char*)qwu,
        hbuf, I_DIM, H_DIM, as1, ws);

    // launch 5: FWHT(8192) + int8 quant of h
    fwht_quant<I_DIM, 512><<<T_TOK, 512>>>(hbuf, qx2, as2, NORM_8192);

    // launch 6: out = hq @ Wd^T
    gemm_imma<<<dim3(H_DIM / 128, T_TOK / 128), 256, GEMM_SMEM>>>(
        (const char*)qx2, (const char*)qwd, out, H_DIM, I_DIM, as2, ws + 2);
}

// round 17
// speedup vs baseline: 1.1081x; 1.1081x over previous
#include <cuda_runtime.h>
#include <cuda_bf16.h>
#include <math.h>
#include <stdint.h>

// ---------------------------------------------------------------------------
// BitNetV3 MLP, round 17: HYBRID GEMM — each 128x128 output tile is computed
// either by the IMMA tensor-core path (R11) or the dp4a FMA-pipe path (R6),
// selected per-block so co-resident CTAs drive DIFFERENT pipes concurrently.
// Both paths are bit-exact integer => identical results to R11/R6.
// out = BitLinear(silu(BitLinear(x,Wg)) * BitLinear(x,Wu), Wd)
// T=4096 tokens, H=2048, I=8192.
// ---------------------------------------------------------------------------

#define T_TOK 4096
#define H_DIM 2048
#define I_DIM 8192

#define NORM_2048 0.022097086912079608f   // 1/sqrt(2048)
#define NORM_8192 0.011048543456039804f   // 1/sqrt(8192)

// ------------------------- scratch (allocation-free) -----------------------
__device__ __align__(16) int    g_qx1[T_TOK * H_DIM / 4];            //  8 MB
__device__ __align__(16) int    g_qx2[T_TOK * I_DIM / 4];            // 32 MB
__device__ float  g_as1[T_TOK];
__device__ float  g_as2[T_TOK];
__device__ __align__(16) int    g_qwg[I_DIM * H_DIM / 4];            // 16 MB
__device__ __align__(16) int    g_qwu[I_DIM * H_DIM / 4];            // 16 MB
__device__ __align__(16) int    g_qwd[H_DIM * I_DIM / 4];            // 16 MB
__device__ float  g_ws[4];
__device__ float  g_part[3 * 512];
__device__ float  g_gate[(size_t)T_TOK * I_DIM];                     // 128 MB

// ----------------------------- PTX helpers ---------------------------------
__device__ __forceinline__ uint32_t s2u(const void* p) {
    uint32_t a;
    asm("{ .reg .u64 t; cvta.to.shared.u64 t, %1; cvt.u32.u64 %0, t; }"
        : "=r"(a) : "l"(p));
    return a;
}
__device__ __forceinline__ void cp16(uint32_t d, const void* s) {
    asm volatile("cp.async.cg.shared.global [%0], [%1], 16;" :: "r"(d), "l"(s));
}
__device__ __forceinline__ void cp_commit() { asm volatile("cp.async.commit_group;"); }
__device__ __forceinline__ void cp_wait1()  { asm volatile("cp.async.wait_group 1;"); }

__device__ __forceinline__ void ldm_x4(uint32_t* r, uint32_t addr) {
    asm volatile("ldmatrix.sync.aligned.m8n8.x4.shared.b16 {%0,%1,%2,%3}, [%4];"
                 : "=r"(r[0]), "=r"(r[1]), "=r"(r[2]), "=r"(r[3]) : "r"(addr));
}
__device__ __forceinline__ void mma_s8(int* d, const uint32_t* a,
                                       uint32_t b0, uint32_t b1) {
    asm volatile(
        "mma.sync.aligned.m16n8k32.row.col.s32.s8.s8.s32 "
        "{%0,%1,%2,%3}, {%4,%5,%6,%7}, {%8,%9}, {%0,%1,%2,%3};"
        : "+r"(d[0]), "+r"(d[1]), "+r"(d[2]), "+r"(d[3])
        : "r"(a[0]), "r"(a[1]), "r"(a[2]), "r"(a[3]), "r"(b0), "r"(b1));
}

// --------------- batched weight prep (3 weights in 3 launches) -------------
__global__ void abs_sum_all(const float4* __restrict__ w0,
                            const float4* __restrict__ w1,
                            const float4* __restrict__ w2,
                            int n4, float* __restrict__ part) {
    const float4* w = (blockIdx.y == 0) ? w0 : (blockIdx.y == 1) ? w1 : w2;
    float s0 = 0.f, s1 = 0.f, s2 = 0.f, s3 = 0.f;
    int i = blockIdx.x * 256 + threadIdx.x;
    const int stride = 512 * 256;
    for (; i + 3 * stride < n4; i += 4 * stride) {
        float4 a = w[i];
        float4 b = w[i + stride];
        float4 c = w[i + 2 * stride];
        float4 d = w[i + 3 * stride];
        s0 += fabsf(a.x) + fabsf(a.y) + fabsf(a.z) + fabsf(a.w);
        s1 += fabsf(b.x) + fabsf(b.y) + fabsf(b.z) + fabsf(b.w);
        s2 += fabsf(c.x) + fabsf(c.y) + fabsf(c.z) + fabsf(c.w);
        s3 += fabsf(d.x) + fabsf(d.y) + fabsf(d.z) + fabsf(d.w);
    }
    for (; i < n4; i += stride) {
        float4 a = w[i];
        s0 += fabsf(a.x) + fabsf(a.y) + fabsf(a.z) + fabsf(a.w);
    }
    __shared__ float red[256];
    red[threadIdx.x] = (s0 + s1) + (s2 + s3);
    __syncthreads();
    for (int off = 128; off > 0; off >>= 1) {
        if ((int)threadIdx.x < off) red[threadIdx.x] += red[threadIdx.x + off];
        __syncthreads();
    }
    if (threadIdx.x == 0) part[blockIdx.y * 512 + blockIdx.x] = red[0];
}

__global__ void abs_final_all(const float* __restrict__ part, long long n,
                              float* __restrict__ ws) {
    __shared__ double red[256];
    double s = 0.0;
    for (int i = threadIdx.x; i < 512; i += 256)
        s += (double)part[blockIdx.x * 512 + i];
    red[threadIdx.x] = s;
    __syncthreads();
    for (int off = 128; off > 0; off >>= 1) {
        if ((int)threadIdx.x < off) red[threadIdx.x] += red[threadIdx.x + off];
        __syncthreads();
    }
    if (threadIdx.x == 0)
        ws[blockIdx.x] = fmaxf((float)(red[0] / (double)n), 1e-5f);
}

__global__ void quant_pack_all(const float* __restrict__ w0,
                               const float* __restrict__ w1,
                               const float* __restrict__ w2,
                               const float* __restrict__ sc,
                               int* __restrict__ q0, int* __restrict__ q1,
                               int* __restrict__ q2, int n4) {
    int i = blockIdx.x * 256 + threadIdx.x;
    if (i >= n4) return;
    const int which = blockIdx.y;
    const float* w = (which == 0) ? w0 : (which == 1) ? w1 : w2;
    int* q = (which == 0) ? q0 : (which == 1) ? q1 : q2;
    float s = sc[which];
    float4 v = reinterpret_cast<const float4*>(w)[i];
    int a = (int)fminf(fmaxf(rintf(v.x / s), -1.f), 1.f);
    int b = (int)fminf(fmaxf(rintf(v.y / s), -1.f), 1.f);
    int c = (int)fminf(fmaxf(rintf(v.z / s), -1.f), 1.f);
    int d = (int)fminf(fmaxf(rintf(v.w / s), -1.f), 1.f);
    q[i] = (a & 0xFF) | ((b & 0xFF) << 8) | ((c & 0xFF) << 16) | ((d & 0xFF) << 24);
}

// --------------- FWHT (last axis) + per-token int8 quant + pack ------------
template <int N, int TPB>
__global__ void fwht_quant(const float* __restrict__ X, int* __restrict__ Q,
                           float* __restrict__ scales, float norm) {
    __shared__ float s[N];
    __shared__ float red[TPB];
    const int t = blockIdx.x;
    const float* x = X + (size_t)t * N;

    for (int i = threadIdx.x; i < N; i += TPB) s[i] = x[i];
    __syncthreads();

    for (int h = 1; h < N; h <<= 1) {
        for (int p = threadIdx.x; p < N / 2; p += TPB) {
            int i = ((p & ~(h - 1)) << 1) | (p & (h - 1));
            float a = s[i], b = s[i + h];
            s[i] = a + b;
            s[i + h] = a - b;
        }
        __syncthreads();
    }

    float m = 0.f;
    for (int i = threadIdx.x; i < N; i += TPB)
        m = fmaxf(m, fabsf(s[i] * norm));
    red[threadIdx.x] = m;
    __syncthreads();
    for (int off = TPB / 2; off > 0; off >>= 1) {
        if ((int)threadIdx.x < off)
            red[threadIdx.x] = fmaxf(red[threadIdx.x], red[threadIdx.x + off]);
        __syncthreads();
    }
    float scale = 127.f / fmaxf(red[0], 1e-5f);
    if (threadIdx.x == 0) scales[t] = scale;

    for (int i = threadIdx.x; i < N / 4; i += TPB) {
        float v0 = s[4 * i + 0] * norm * scale;
        float v1 = s[4 * i + 1] * norm * scale;
        float v2 = s[4 * i + 2] * norm * scale;
        float v3 = s[4 * i + 3] * norm * scale;
        int q0 = (int)fminf(fmaxf(rintf(v0), -128.f), 127.f);
        int q1 = (int)fminf(fmaxf(rintf(v1), -128.f), 127.f);
        int q2 = (int)fminf(fmaxf(rintf(v2), -128.f), 127.f);
        int q3 = (int)fminf(fmaxf(rintf(v3), -128.f), 127.f);
        Q[(size_t)t * (N / 4) + i] = (q0 & 0xFF) | ((q1 & 0xFF) << 8)
                                   | ((q2 & 0xFF) << 16) | ((q3 & 0xFF) << 24);
    }
}

// ------------------------ HYBRID int8 GEMM ---------------------------------
// Each 128x128 tile goes to ONE engine:
//   imma path: R11 mainloop (3-stage cp.async ring, ldmatrix, mma.sync) —
//              tensor pipe.
//   dp4a path: R6 mainloop (smem int32 tiles, __dp4a register blocking) —
//              fma pipe.
// Classifier flips under +148 so the 2 co-resident CTAs/SM mix engines.
// C[t,o] = acc * wS / actScale[t]. MODE 1: C holds gate; write silu(gate)*up.
#define STAGE_BYTES 32768
#define GEMM_SMEM   (3 * STAGE_BYTES)

template <int MODE>
__global__ __launch_bounds__(256, 2)
void gemm_hybrid(const char* __restrict__ A,   // [M_total][K] int8 row-major
                 const char* __restrict__ Bw,  // [O][K]      int8 row-major
                 float* __restrict__ C,        // [M_total][O] f32
                 int O, int K,
                 const float* __restrict__ actScale,
                 const float* __restrict__ wScale) {
    extern __shared__ __align__(1024) char smem[];

    const int tid = threadIdx.x;
    const int lane = tid & 31, w = tid >> 5;
    const int blockM = blockIdx.y * 128, blockN = blockIdx.x * 128;
    const int bid = blockIdx.y * gridDim.x + blockIdx.x;
    const bool use_dp4a = (((bid >> 2) & 7) < 3);   // 3/8 of tile-groups

    const float wS = wScale[0];

    if (!use_dp4a) {
        // ================= IMMA path (identical to round 11) ================
        const uint32_t S0 = s2u(smem);
        const int wm = w >> 1, wn = w & 1;

        const int aRow = wm * 32 + (lane & 7) + ((lane >> 3) & 1) * 8;
        const uint32_t aKh = ((lane >> 4) & 1) * 16;
        const uint32_t aQ  = (uint32_t)(aRow & 7) << 4;
        const int bRow = wn * 64 + (lane & 7) + ((lane >> 4) & 1) * 8;
        const uint32_t bKh = ((lane >> 3) & 1) * 16;
        const uint32_t bQ  = (uint32_t)(bRow & 7) << 4;

        int acc[2][8][4];
#pragma unroll
        for (int i = 0; i < 2; i++)
#pragma unroll
            for (int j = 0; j < 8; j++)
#pragma unroll
                for (int k = 0; k < 4; k++) acc[i][j][k] = 0;

        const char* gA = A  + (size_t)blockM * K;
        const char* gB = Bw + (size_t)blockN * K;
        const int nC = K >> 7;

#define LOAD_CHUNK(stage, kt)                                                 \
        do {                                                                  \
            const uint32_t dA = S0 + (stage) * STAGE_BYTES;                   \
            const uint32_t dB = dA + 16384;                                   \
            _Pragma("unroll")                                                 \
            for (int i = 0; i < 4; i++) {                                     \
                int g = i * 256 + tid;                                        \
                uint32_t off = (uint32_t)g * 16;                              \
                uint32_t sw = off ^ ((off >> 3) & 0x70);                      \
                int row = g >> 3, cc = (g & 7) * 16;                          \
                cp16(dA + sw, gA + (size_t)row * K + (kt) + cc);              \
                cp16(dB + sw, gB + (size_t)row * K + (kt) + cc);              \
            }                                                                 \
            cp_commit();                                                      \
        } while (0)

        LOAD_CHUNK(0, 0);

        int st = 0;
        for (int c = 0; c < nC; c++) {
            if (c + 1 < nC) {
                int ns = st + 1; if (ns == 3) ns = 0;
                LOAD_CHUNK(ns, (c + 1) << 7);
            } else {
                cp_commit();
            }
            cp_wait1();
            __syncthreads();

            const uint32_t aBase = S0 + st * STAGE_BYTES + (uint32_t)aRow * 128;
            const uint32_t bBase = S0 + st * STAGE_BYTES + 16384 + (uint32_t)bRow * 128;
#pragma unroll
            for (int ks = 0; ks < 4; ks++) {
                uint32_t Af[2][4], Bf[4][4];
#pragma unroll
                for (int mr = 0; mr < 2; mr++)
                    ldm_x4(Af[mr], aBase + mr * (16 * 128)
                                   + (((uint32_t)(ks * 32) + aKh) ^ aQ));
#pragma unroll
                for (int ng = 0; ng < 4; ng++)
                    ldm_x4(Bf[ng], bBase + ng * (16 * 128)
                                   + (((uint32_t)(ks * 32) + bKh) ^ bQ));
#pragma unroll
                for (int mr = 0; mr < 2; mr++)
#pragma unroll
                    for (int nb = 0; nb < 8; nb++)
                        mma_s8(acc[mr][nb], Af[mr],
                               Bf[nb >> 1][(nb & 1) * 2],
                               Bf[nb >> 1][(nb & 1) * 2 + 1]);
            }
            if (++st == 3) st = 0;
        }
#undef LOAD_CHUNK

        const int r = lane >> 2, cq = (lane & 3) * 2;
#pragma unroll
        for (int mr = 0; mr < 2; mr++) {
#pragma unroll
            for (int half = 0; half < 2; half++) {
                const int m = blockM + wm * 32 + mr * 16 + half * 8 + r;
                const float f = wS / __ldg(&actScale[m]);
                float* crow = C + (size_t)m * O + blockN + wn * 64;
#pragma unroll
                for (int nb = 0; nb < 8; nb++) {
                    float2 v;
                    v.x = (float)acc[mr][nb][half * 2]     * f;
                    v.y = (float)acc[mr][nb][half * 2 + 1] * f;
                    float* p = crow + nb * 8 + cq;
                    if (MODE == 1) {
                        float2 g = *reinterpret_cast<const float2*>(p);
                        v.x *= g.x / (1.f + expf(-g.x));
                        v.y *= g.y / (1.f + expf(-g.y));
                    }
                    *reinterpret_cast<float2*>(p) = v;
                }
            }
        }
    } else {
        // ================= dp4a path (identical math to round 6) ===========
        int* As = (int*)smem;              // [16][128]
        int* Bs = As + 16 * 128;           // [16][128]
        const int* Ai = (const int*)A;
        const int* Bi = (const int*)Bw;
        const int Kp = K >> 2;

        const int tx = tid & 15, ty = tid >> 4;
        int acc[8][8];
#pragma unroll
        for (int i = 0; i < 8; i++)
#pragma unroll
            for (int j = 0; j < 8; j++) acc[i][j] = 0;

        const int ldr = tid >> 2;          // 0..63
        const int ldc = (tid & 3) * 4;     // 0,4,8,12

        for (int kt = 0; kt < Kp; kt += 16) {
#pragma unroll
            for (int rr = 0; rr < 2; rr++) {
                int r = ldr + rr * 64;
                int4 va = *reinterpret_cast<const int4*>(
                    &Ai[(size_t)(blockM + r) * Kp + kt + ldc]);
                As[(ldc + 0) * 128 + r] = va.x; As[(ldc + 1) * 128 + r] = va.y;
                As[(ldc + 2) * 128 + r] = va.z; As[(ldc + 3) * 128 + r] = va.w;
                int4 vb = *reinterpret_cast<const int4*>(
                    &Bi[(size_t)(blockN + r) * Kp + kt + ldc]);
                Bs[(ldc + 0) * 128 + r] = vb.x; Bs[(ldc + 1) * 128 + r] = vb.y;
                Bs[(ldc + 2) * 128 + r] = vb.z; Bs[(ldc + 3) * 128 + r] = vb.w;
            }
            __syncthreads();

#pragma unroll
            for (int kk = 0; kk < 16; kk++) {
                int4 a0 = *reinterpret_cast<const int4*>(&As[kk * 128 + ty * 8]);
                int4 a1 = *reinterpret_cast<const int4*>(&As[kk * 128 + ty * 8 + 4]);
                int4 b0 = *reinterpret_cast<const int4*>(&Bs[kk * 128 + tx * 8]);
                int4 b1 = *reinterpret_cast<const int4*>(&Bs[kk * 128 + tx * 8 + 4]);
                int a[8] = {a0.x, a0.y, a0.z, a0.w, a1.x, a1.y, a1.z, a1.w};
                int b[8] = {b0.x, b0.y, b0.z, b0.w, b1.x, b1.y, b1.z, b1.w};
#pragma unroll
                for (int i = 0; i < 8; i++)
#pragma unroll
                    for (int j = 0; j < 8; j++)
                        acc[i][j] = __dp4a(a[i], b[j], acc[i][j]);
            }
            __syncthreads();
        }

#pragma unroll
        for (int i = 0; i < 8; i++) {
            int m = blockM + ty * 8 + i;
            float f = wS / __ldg(&actScale[m]);
#pragma unroll
            for (int j = 0; j < 8; j++) {
                int o = blockN + tx * 8 + j;
                size_t idx = (size_t)m * O + o;
                float v = (float)acc[i][j] * f;
                if (MODE == 1) {
                    float g = C[idx];
                    v *= g / (1.f + expf(-g));
                }
                C[idx] = v;
            }
        }
    }
}

// ------------------------------- launcher ----------------------------------
extern "C" void kernel_launch(void* const* d_in, const int* in_sizes, int n_in,
                              void* d_out, int out_size) {
    const float* x  = (const float*)d_in[0];
    const float* wg = (const float*)d_in[1];
    const float* wu = (const float*)d_in[2];
    const float* wd = (const float*)d_in[3];
    float* out = (float*)d_out;

    void* p;
    cudaGetSymbolAddress(&p, g_qx1);  int*   qx1  = (int*)p;
    cudaGetSymbolAddress(&p, g_qx2);  int*   qx2  = (int*)p;
    cudaGetSymbolAddress(&p, g_as1);  float* as1  = (float*)p;
    cudaGetSymbolAddress(&p, g_as2);  float* as2  = (float*)p;
    cudaGetSymbolAddress(&p, g_qwg);  int*   qwg  = (int*)p;
    cudaGetSymbolAddress(&p, g_qwu);  int*   qwu  = (int*)p;
    cudaGetSymbolAddress(&p, g_qwd);  int*   qwd  = (int*)p;
    cudaGetSymbolAddress(&p, g_ws);   float* ws   = (float*)p;
    cudaGetSymbolAddress(&p, g_part); float* part = (float*)p;
    cudaGetSymbolAddress(&p, g_gate); float* gate = (float*)p;

    cudaFuncSetAttribute(gemm_hybrid<0>, cudaFuncAttributeMaxDynamicSharedMemorySize, GEMM_SMEM);
    cudaFuncSetAttribute(gemm_hybrid<1>, cudaFuncAttributeMaxDynamicSharedMemorySize, GEMM_SMEM);

    const long long nW = (long long)I_DIM * H_DIM;
    const int n4 = (int)(nW / 4);

    // launches 0-2: weight scales + ternary pack
    abs_sum_all<<<dim3(512, 3), 256>>>((const float4*)wg, (const float4*)wu,
                                       (const float4*)wd, n4, part);
    abs_final_all<<<3, 256>>>(part, nW, ws);
    quant_pack_all<<<dim3((n4 + 255) / 256, 3), 256>>>(wg, wu, wd, ws,
                                                       qwg, qwu, qwd, n4);

    // launch 3: FWHT(2048) + int8 quant of input (shared by gate & up)
    fwht_quant<H_DIM, 256><<<T_TOK, 256>>>(x, qx1, as1, NORM_2048);

    // launches 4-5: gate = xq@Wg^T, then h = silu(gate)*(xq@Wu^T) fused
    gemm_hybrid<0><<<dim3(I_DIM / 128, T_TOK / 128), 256, GEMM_SMEM>>>(
        (const char*)qx1, (const char*)qwg, gate, I_DIM, H_DIM, as1, ws + 0);
    gemm_hybrid<1><<<dim3(I_DIM / 128, T_TOK / 128), 256, GEMM_SMEM>>>(
        (const char*)qx1, (const char*)qwu, gate, I_DIM, H_DIM, as1, ws + 1);

    // launch 6: FWHT(8192) + int8 quant of h
    fwht_quant<I_DIM, 512><<<T_TOK, 512>>>(gate, qx2, as2, NORM_8192);

    // launch 7: out = hq @ Wd^T
    gemm_hybrid<0><<<dim3(H_DIM / 128, T_TOK / 128), 256, GEMM_SMEM>>>(
        (const char*)qx2, (const char*)qwd, out, H_DIM, I_DIM, as2, ws + 2);
}